// round 16
// baseline (speedup 1.0000x reference)
#include <cuda_runtime.h>
#include <cstdint>

#define SEQ 4096
#define DM  1024
#define NH  16
#define HD  64

// Scratch (allocation inside kernel_launch is forbidden).
static __device__ float g_Q [SEQ * DM];
static __device__ float g_K [SEQ * DM];
static __device__ float g_V [SEQ * DM];
static __device__ float g_AO[SEQ * DM];

// ---------------------------------------------------------------------------
// Packed fp32x2 helpers
// ---------------------------------------------------------------------------
typedef unsigned long long u64t;

__device__ __forceinline__ void ffma2(u64t& d, u64t a, u64t b) {
    asm("fma.rn.f32x2 %0, %1, %2, %0;" : "+l"(d) : "l"(a), "l"(b));
}
__device__ __forceinline__ void fmul2(u64t& d, u64t a, u64t b) {
    asm("mul.rn.f32x2 %0, %1, %2;" : "=l"(d) : "l"(a), "l"(b));
}
__device__ __forceinline__ u64t packdup(float x) {
    u64t r;
    asm("mov.b64 %0, {%1, %1};" : "=l"(r) : "f"(x));
    return r;
}
__device__ __forceinline__ void unpack2(float& lo, float& hi, u64t v) {
    asm("mov.b64 {%0, %1}, %2;" : "=f"(lo), "=f"(hi) : "l"(v));
}

// Warp-shape remap: warp covers 4 rows x 8 cols so BOTH operands get
// intra-warp broadcast (A: 8-way, B: 4-way) -> fewer LDS wavefronts.
__device__ __forceinline__ void tile_map(int tid, int& tm, int& tn) {
    const int w = tid >> 5;
    const int l = tid & 31;
    tm = (w & 3) * 4 + (l >> 3);   // 0..15
    tn = (w >> 2) * 8 + (l & 7);   // 0..15
}

// ---------------------------------------------------------------------------
// GEMM core: C[M,N] = A[M,K] @ W[N,K]^T + bias[N]
// 128x128 block tile, K-tile 16, 256 threads, 8x8 micro-tile, f32x2 FMAs.
// ---------------------------------------------------------------------------
__device__ __forceinline__ void gemm_core(
    const float* __restrict__ A, const float* __restrict__ W,
    const float* __restrict__ bias, float* __restrict__ C,
    int M, int N, int K, int bm, int bn)
{
    __shared__ float As[16][132];
    __shared__ float Ws[16][132];

    const int tid = threadIdx.x;
    int tm, tn;
    tile_map(tid, tm, tn);

    const int i0  = tid * 2;
    const int ar0 = i0 >> 2,       ac0 = (i0 & 3) << 2;
    const int ar1 = (i0 + 1) >> 2, ac1 = ((i0 + 1) & 3) << 2;

    const float* Ab = A + (size_t)bm * 128 * K;
    const float* Wb = W + (size_t)bn * 128 * K;

    u64t acc2[4][8];
    #pragma unroll
    for (int i = 0; i < 4; i++)
        #pragma unroll
        for (int j = 0; j < 8; j++) acc2[i][j] = 0ull;

    const int NK = K >> 4;

    float4 a0 = *(const float4*)(Ab + (size_t)ar0 * K + ac0);
    float4 a1 = *(const float4*)(Ab + (size_t)ar1 * K + ac1);
    float4 w0 = *(const float4*)(Wb + (size_t)ar0 * K + ac0);
    float4 w1 = *(const float4*)(Wb + (size_t)ar1 * K + ac1);
    As[ac0+0][ar0] = a0.x; As[ac0+1][ar0] = a0.y; As[ac0+2][ar0] = a0.z; As[ac0+3][ar0] = a0.w;
    As[ac1+0][ar1] = a1.x; As[ac1+1][ar1] = a1.y; As[ac1+2][ar1] = a1.z; As[ac1+3][ar1] = a1.w;
    Ws[ac0+0][ar0] = w0.x; Ws[ac0+1][ar0] = w0.y; Ws[ac0+2][ar0] = w0.z; Ws[ac0+3][ar0] = w0.w;
    Ws[ac1+0][ar1] = w1.x; Ws[ac1+1][ar1] = w1.y; Ws[ac1+2][ar1] = w1.z; Ws[ac1+3][ar1] = w1.w;
    __syncthreads();

    for (int kt = 0; kt < NK; kt++) {
        const bool more = (kt + 1 < NK);
        float4 na0, na1, nw0, nw1;
        if (more) {
            const float* Ap = Ab + (kt + 1) * 16;
            const float* Wp = Wb + (kt + 1) * 16;
            na0 = *(const float4*)(Ap + (size_t)ar0 * K + ac0);
            na1 = *(const float4*)(Ap + (size_t)ar1 * K + ac1);
            nw0 = *(const float4*)(Wp + (size_t)ar0 * K + ac0);
            nw1 = *(const float4*)(Wp + (size_t)ar1 * K + ac1);
        }

        #pragma unroll
        for (int kk = 0; kk < 16; kk++) {
            ulonglong2 av0 = *(const ulonglong2*)&As[kk][tm * 8];
            ulonglong2 av1 = *(const ulonglong2*)&As[kk][tm * 8 + 4];
            u64t a2[4] = {av0.x, av0.y, av1.x, av1.y};
            float4 bv0 = *(const float4*)&Ws[kk][tn * 8];
            float4 bv1 = *(const float4*)&Ws[kk][tn * 8 + 4];
            u64t bd[8];
            bd[0] = packdup(bv0.x); bd[1] = packdup(bv0.y);
            bd[2] = packdup(bv0.z); bd[3] = packdup(bv0.w);
            bd[4] = packdup(bv1.x); bd[5] = packdup(bv1.y);
            bd[6] = packdup(bv1.z); bd[7] = packdup(bv1.w);
            #pragma unroll
            for (int i = 0; i < 4; i++)
                #pragma unroll
                for (int j = 0; j < 8; j++)
                    ffma2(acc2[i][j], a2[i], bd[j]);
        }
        __syncthreads();
        if (more) {
            As[ac0+0][ar0] = na0.x; As[ac0+1][ar0] = na0.y; As[ac0+2][ar0] = na0.z; As[ac0+3][ar0] = na0.w;
            As[ac1+0][ar1] = na1.x; As[ac1+1][ar1] = na1.y; As[ac1+2][ar1] = na1.z; As[ac1+3][ar1] = na1.w;
            Ws[ac0+0][ar0] = nw0.x; Ws[ac0+1][ar0] = nw0.y; Ws[ac0+2][ar0] = nw0.z; Ws[ac0+3][ar0] = nw0.w;
            Ws[ac1+0][ar1] = nw1.x; Ws[ac1+1][ar1] = nw1.y; Ws[ac1+2][ar1] = nw1.z; Ws[ac1+3][ar1] = nw1.w;
        }
        __syncthreads();
    }

    const int row0 = bm * 128 + tm * 8;
    const int col0 = bn * 128 + tn * 8;
    float bb[8];
    #pragma unroll
    for (int j = 0; j < 8; j++) bb[j] = bias[col0 + j];
    #pragma unroll
    for (int ip = 0; ip < 4; ip++) {
        float r0[8], r1[8];
        #pragma unroll
        for (int j = 0; j < 8; j++) unpack2(r0[j], r1[j], acc2[ip][j]);
        const int r = row0 + 2 * ip;
        *(float4*)&C[(size_t)r * N + col0] =
            make_float4(r0[0] + bb[0], r0[1] + bb[1], r0[2] + bb[2], r0[3] + bb[3]);
        *(float4*)&C[(size_t)r * N + col0 + 4] =
            make_float4(r0[4] + bb[4], r0[5] + bb[5], r0[6] + bb[6], r0[7] + bb[7]);
        *(float4*)&C[(size_t)(r + 1) * N + col0] =
            make_float4(r1[0] + bb[0], r1[1] + bb[1], r1[2] + bb[2], r1[3] + bb[3]);
        *(float4*)&C[(size_t)(r + 1) * N + col0 + 4] =
            make_float4(r1[4] + bb[4], r1[5] + bb[5], r1[6] + bb[6], r1[7] + bb[7]);
    }
}

// Merged QKV projection: blockIdx.z selects (input, weight, bias, output).
__global__ void __launch_bounds__(256, 2)
gemm_qkv(const float* __restrict__ Aq, const float* __restrict__ Ak, const float* __restrict__ Av,
         const float* __restrict__ Wq, const float* __restrict__ Wk, const float* __restrict__ Wv,
         const float* __restrict__ bq, const float* __restrict__ bk, const float* __restrict__ bv,
         float* __restrict__ Cq, float* __restrict__ Ck, float* __restrict__ Cv,
         int M, int N, int K)
{
    const int z = blockIdx.z;
    const float* A = (z == 0) ? Aq : (z == 1) ? Ak : Av;
    const float* W = (z == 0) ? Wq : (z == 1) ? Wk : Wv;
    const float* b = (z == 0) ? bq : (z == 1) ? bk : bv;
    float*       C = (z == 0) ? Cq : (z == 1) ? Ck : Cv;
    gemm_core(A, W, b, C, M, N, K, blockIdx.y, blockIdx.x);
}

__global__ void __launch_bounds__(256, 2)
gemm_bias(const float* __restrict__ A, const float* __restrict__ W,
          const float* __restrict__ bias, float* __restrict__ C,
          int M, int N, int K)
{
    gemm_core(A, W, bias, C, M, N, K, blockIdx.y, blockIdx.x);
}

// ---------------------------------------------------------------------------
// Causal flash attention, fp32. BQ=BK=128, 256 threads.
// Micro-tiles: QK^T 8q x 8k per thread; PV 8q x 4v per thread.
// S stored row-major [q][k]; warp shape 4x8 for broadcast on both operands.
// ---------------------------------------------------------------------------
#define DP 132                      // Qs/Ks pitch ([d][q] / [d][k])
#define SP 132                      // Ss pitch    ([q][k])
#define VPCH 68                     // Vs pitch    ([k][v])
#define FLASH_SMEM ((64*DP*2 + 128*VPCH + 128*SP + 3*128) * 4)   // 171,520 B

__global__ void __launch_bounds__(256, 1)
flash_attn()
{
    extern __shared__ float smf[];
    float* Qs  = smf;                  // [d][q]  64 x DP (pre-scaled by 1/8)
    float* Ks  = Qs + 64 * DP;         // [d][k]  64 x DP
    float* Vs  = Ks + 64 * DP;         // [k][v] 128 x VPCH
    float* Ss  = Vs + 128 * VPCH;      // [q][k] 128 x SP
    float* m_s = Ss + 128 * SP;
    float* l_s = m_s + 128;
    float* a_s = l_s + 128;

    const int tid = threadIdx.x;
    int tm, tn;
    tile_map(tid, tm, tn);             // q rows tm*8..+7 ; k cols tn*8..+7 / v cols tn*4..+3
    const int h   = blockIdx.y;
    const int qt  = (int)gridDim.x - 1 - (int)blockIdx.x;  // longest-first
    const int q0  = qt * 128;
    const size_t hoff = (size_t)h * HD;

    // Load Q tile (128 x 64) transposed to [d][q], fused 1/sqrt(64) scale.
#pragma unroll
    for (int s = 0; s < 8; s++) {
        int idx = tid + 256 * s;
        int r = idx >> 4;
        int c = (idx & 15) << 2;
        float4 q4 = *(const float4*)&g_Q[(size_t)(q0 + r) * DM + hoff + c];
        Qs[(c + 0) * DP + r] = q4.x * 0.125f;
        Qs[(c + 1) * DP + r] = q4.y * 0.125f;
        Qs[(c + 2) * DP + r] = q4.z * 0.125f;
        Qs[(c + 3) * DP + r] = q4.w * 0.125f;
    }
    if (tid < 128) { m_s[tid] = -1e30f; l_s[tid] = 0.f; }

    // O accumulators: 8 q rows x 4 v cols, packed over v (2 x f32x2 per row).
    u64t o2[8][2] = {};

    for (int kt = 0; kt <= qt; kt++) {
        const int k0 = kt * 128;
        __syncthreads();   // prior tile's PV reads complete before overwrite

        // Load K (transposed [d][k]) and V ([k][v]) tiles.
#pragma unroll
        for (int s = 0; s < 8; s++) {
            int idx = tid + 256 * s;
            int r = idx >> 4;
            int c = (idx & 15) << 2;
            float4 k4 = *(const float4*)&g_K[(size_t)(k0 + r) * DM + hoff + c];
            Ks[(c + 0) * DP + r] = k4.x;
            Ks[(c + 1) * DP + r] = k4.y;
            Ks[(c + 2) * DP + r] = k4.z;
            Ks[(c + 3) * DP + r] = k4.w;
            float4 v4 = *(const float4*)&g_V[(size_t)(k0 + r) * DM + hoff + c];
            *(float4*)&Vs[r * VPCH + c] = v4;
        }
        __syncthreads();

        // S = (Q/8) K^T : 8x8 per thread, q-pairs x dup-k.
        u64t s2[4][8];
#pragma unroll
        for (int i = 0; i < 4; i++)
#pragma unroll
            for (int j = 0; j < 8; j++) s2[i][j] = 0ull;

#pragma unroll 8
        for (int d = 0; d < 64; d++) {
            ulonglong2 qa = *(const ulonglong2*)&Qs[d * DP + tm * 8];
            ulonglong2 qb = *(const ulonglong2*)&Qs[d * DP + tm * 8 + 4];
            u64t q2[4] = {qa.x, qa.y, qb.x, qb.y};
            float4 kv0 = *(const float4*)&Ks[d * DP + tn * 8];
            float4 kv1 = *(const float4*)&Ks[d * DP + tn * 8 + 4];
            u64t kd[8];
            kd[0] = packdup(kv0.x); kd[1] = packdup(kv0.y);
            kd[2] = packdup(kv0.z); kd[3] = packdup(kv0.w);
            kd[4] = packdup(kv1.x); kd[5] = packdup(kv1.y);
            kd[6] = packdup(kv1.z); kd[7] = packdup(kv1.w);
#pragma unroll
            for (int i = 0; i < 4; i++)
#pragma unroll
                for (int j = 0; j < 8; j++)
                    ffma2(s2[i][j], q2[i], kd[j]);
        }

        float sacc[8][8];
#pragma unroll
        for (int i = 0; i < 4; i++)
#pragma unroll
            for (int j = 0; j < 8; j++)
                unpack2(sacc[2 * i][j], sacc[2 * i + 1][j], s2[i][j]);

        // Causal mask only on the diagonal tile.
        if (kt == qt) {
#pragma unroll
            for (int i = 0; i < 8; i++)
#pragma unroll
                for (int j = 0; j < 8; j++)
                    if (tn * 8 + j > tm * 8 + i) sacc[i][j] = -1e30f;
        }

        // Store S row-major [q][k].
#pragma unroll
        for (int i = 0; i < 8; i++) {
            *(float4*)&Ss[(tm * 8 + i) * SP + tn * 8] =
                make_float4(sacc[i][0], sacc[i][1], sacc[i][2], sacc[i][3]);
            *(float4*)&Ss[(tm * 8 + i) * SP + tn * 8 + 4] =
                make_float4(sacc[i][4], sacc[i][5], sacc[i][6], sacc[i][7]);
        }
        __syncthreads();

        // Online softmax: thread q handles its contiguous row.
        if (tid < 128) {
            float mi = m_s[tid];
            float mx = mi;
#pragma unroll 8
            for (int kb = 0; kb < 32; kb++) {
                float4 sv = *(const float4*)&Ss[tid * SP + kb * 4];
                mx = fmaxf(mx, fmaxf(fmaxf(sv.x, sv.y), fmaxf(sv.z, sv.w)));
            }
            float alpha = __expf(mi - mx);
            float sum = 0.f;
#pragma unroll 8
            for (int kb = 0; kb < 32; kb++) {
                float4 sv = *(float4*)&Ss[tid * SP + kb * 4];
                sv.x = __expf(sv.x - mx); sv.y = __expf(sv.y - mx);
                sv.z = __expf(sv.z - mx); sv.w = __expf(sv.w - mx);
                *(float4*)&Ss[tid * SP + kb * 4] = sv;
                sum += (sv.x + sv.y) + (sv.z + sv.w);
            }
            m_s[tid] = mx;
            l_s[tid] = l_s[tid] * alpha + sum;
            a_s[tid] = alpha;
        }
        __syncthreads();

        // Rescale running O by alpha.
#pragma unroll
        for (int i = 0; i < 8; i++) {
            u64t ad = packdup(a_s[tm * 8 + i]);
            fmul2(o2[i][0], o2[i][0], ad);
            fmul2(o2[i][1], o2[i][1], ad);
        }

        // O += P @ V : per 4-j block, P rows read as float4, V as v-pairs.
#pragma unroll 4
        for (int jb = 0; jb < 32; jb++) {
            float pr[8][4];
#pragma unroll
            for (int i = 0; i < 8; i++) {
                float4 p4 = *(const float4*)&Ss[(tm * 8 + i) * SP + jb * 4];
                pr[i][0] = p4.x; pr[i][1] = p4.y; pr[i][2] = p4.z; pr[i][3] = p4.w;
            }
#pragma unroll
            for (int jj = 0; jj < 4; jj++) {
                const int j = jb * 4 + jj;
                ulonglong2 vv = *(const ulonglong2*)&Vs[j * VPCH + tn * 4];
#pragma unroll
                for (int i = 0; i < 8; i++) {
                    u64t pd = packdup(pr[i][jj]);
                    ffma2(o2[i][0], pd, vv.x);
                    ffma2(o2[i][1], pd, vv.y);
                }
            }
        }
    }

    // Epilogue: normalize and write [q, h*HD + v].
#pragma unroll
    for (int i = 0; i < 8; i++) {
        float inv = 1.f / l_s[tm * 8 + i];
        float oa, ob, oc, od;
        unpack2(oa, ob, o2[i][0]);
        unpack2(oc, od, o2[i][1]);
        *(float4*)&g_AO[(size_t)(q0 + tm * 8 + i) * DM + hoff + tn * 4] =
            make_float4(oa * inv, ob * inv, oc * inv, od * inv);
    }
}

// ---------------------------------------------------------------------------
extern "C" void kernel_launch(void* const* d_in, const int* in_sizes, int n_in,
                              void* d_out, int out_size)
{
    const float* queries = (const float*)d_in[0];
    const float* keys    = (const float*)d_in[1];
    const float* values  = (const float*)d_in[2];
    const float* Wq      = (const float*)d_in[3];
    const float* bq      = (const float*)d_in[4];
    const float* Wk      = (const float*)d_in[5];
    const float* bk      = (const float*)d_in[6];
    const float* Wv      = (const float*)d_in[7];
    const float* bv      = (const float*)d_in[8];
    const float* Wo      = (const float*)d_in[9];
    const float* bo      = (const float*)d_in[10];
    float* out = (float*)d_out;

    float *Qp, *Kp, *Vp, *AOp;
    cudaGetSymbolAddress((void**)&Qp,  g_Q);
    cudaGetSymbolAddress((void**)&Kp,  g_K);
    cudaGetSymbolAddress((void**)&Vp,  g_V);
    cudaGetSymbolAddress((void**)&AOp, g_AO);

    cudaFuncSetAttribute(flash_attn, cudaFuncAttributeMaxDynamicSharedMemorySize,
                         FLASH_SMEM);

    dim3 qkvgrid(DM / 128, SEQ / 128, 3);   // (8, 32, 3)
    gemm_qkv<<<qkvgrid, 256>>>(queries, keys, values,
                               Wq, Wk, Wv, bq, bk, bv,
                               Qp, Kp, Vp, SEQ, DM, DM);

    flash_attn<<<dim3(SEQ / 128, NH), 256, FLASH_SMEM>>>();

    gemm_bias<<<dim3(DM / 128, SEQ / 128), 256>>>(AOp, Wo, bo, out, SEQ, DM, DM);
}